// round 15
// baseline (speedup 1.0000x reference)
#include <cuda_runtime.h>
#include <cstdint>

#define DIM     64
#define CHUNKS  16            // float4 chunks per row
#define NMAX    100000        // nodes per ntype (static scratch sizing)
#define EMAX    500000        // edges per relation
#define KSLOT   40            // slots per bucket (deg ~Poisson(10)); 160B, 16B-aligned
#define SPILLC  (4 * EMAX)    // spill capacity = all edges (unconditional)
#define NOVER_IDX (2 * NMAX)  // overflow counter lives at g_cur[NOVER_IDX]

// entry encoding: bits [8..27] = src*256 (byte offset into embed table),
//                 bit 30 = table flag. Requires src*256 < 2^28 (N < 1M).
#define ENT_OFF_MASK 0x0FFFFFFF
#define ENT_FLAG_BIT (1 << 30)

// ---------------------------------------------------------------------------
// scratch (device globals — no runtime allocation). g_cur[0..2*NMAX) are the
// per-bucket cursors; g_cur[2*NMAX] is the overflow count. One memset clears
// everything before permute.
// ---------------------------------------------------------------------------
__device__ int  g_cur[2 * NMAX + 1];
__device__ int  g_entries[2 * NMAX * KSLOT];  // (src<<8) | (flag<<30), slotted
__device__ int2 g_spill[SPILLC];              // (bucket, entry)

// ---------------------------------------------------------------------------
// index helpers. int64 values in [0,1e5): odd 32-bit words are 0.
// int32 random values: P(4 specific words all 0) ~ 1e-20. Broadcast loads.
// ---------------------------------------------------------------------------
__device__ __forceinline__ int probe_idx64(const unsigned int* __restrict__ w) {
    return ((w[1] | w[3] | w[5] | w[7]) == 0u) ? 1 : 0;
}
__device__ __forceinline__ int load_idx32(const void* p, int i, int idx64) {
    // index values < 2^31: low word suffices for both int32 and int64 layouts
    return idx64 ? ((const int*)p)[2 * i] : ((const int*)p)[i];
}

__device__ __forceinline__ void slot_edge(int b, int ent) {
    int pos = atomicAdd(&g_cur[b], 1);
    if (pos < KSLOT) {
        g_entries[b * KSLOT + pos] = ent;
    } else {
        int spos = atomicAdd(&g_cur[NOVER_IDX], 1);
        g_spill[spos] = make_int2(b, ent);
    }
}

// ---------------------------------------------------------------------------
// 1) permute: ONE thread handles edge e in ALL FOUR relations — fixed
//    overhead (probe/bounds/scheduling) paid once, 8 independent index loads
//    + 4 independent atomic chains (high MLP). Byte/atomic counts unchanged.
//    relation -> (dst ntype, src table): r0:(B,e0) r1:(A,e1) r2:(A,e2) r3:(B,e3)
//    bucket b = ntype*nN + dst; entry carries precomputed byte offset + flag.
// ---------------------------------------------------------------------------
__global__ void __launch_bounds__(256)
permute_kernel(const void* __restrict__ s0, const void* __restrict__ d0,
               const void* __restrict__ s1, const void* __restrict__ d1,
               const void* __restrict__ s2, const void* __restrict__ d2,
               const void* __restrict__ s3, const void* __restrict__ d3,
               int nE, int nN) {
    int e = blockIdx.x * blockDim.x + threadIdx.x;
    if (e >= nE) return;

    const int idx64 = probe_idx64((const unsigned int*)s0);

    // issue all 8 index loads up front (independent)
    int src0 = load_idx32(s0, e, idx64);
    int dst0 = load_idx32(d0, e, idx64);
    int src1 = load_idx32(s1, e, idx64);
    int dst1 = load_idx32(d1, e, idx64);
    int src2 = load_idx32(s2, e, idx64);
    int dst2 = load_idx32(d2, e, idx64);
    int src3 = load_idx32(s3, e, idx64);
    int dst3 = load_idx32(d3, e, idx64);

    // r1: ntype A, table flag 0 ; r2: ntype A, flag 1
    // r0: ntype B, flag 0       ; r3: ntype B, flag 1
    slot_edge(dst1,      (src1 << 8));
    slot_edge(dst2,      (src2 << 8) | ENT_FLAG_BIT);
    slot_edge(nN + dst0, (src0 << 8));
    slot_edge(nN + dst3, (src3 << 8) | ENT_FLAG_BIT);
}

// ---------------------------------------------------------------------------
// 2) accumulate: thread = (bucket, float4-chunk). Seed = bias (broadcast),
//    register-accumulate gathered rows, relu, single streaming store.
//    bucket < nN -> h_A (tables e1/e2), else h_B (tables e0/e3).
//    Entries fetched 4-at-a-time via int4; full groups run unpredicated,
//    only the last group carries per-slot bounds tests.
// ---------------------------------------------------------------------------
__global__ void __launch_bounds__(256)
accum_kernel(const float* __restrict__ e0, const float* __restrict__ e1,
             const float* __restrict__ e2, const float* __restrict__ e3,
             const float4* __restrict__ bias4, float4* __restrict__ out4,
             int nN) {
    int g = blockIdx.x * blockDim.x + threadIdx.x;
    int b = g >> 4;
    int c = g & 15;
    if (b >= 2 * nN) return;

    const char* t0;
    const char* t1;
    if (b < nN) { t0 = (const char*)e1; t1 = (const char*)e2; }  // h_A
    else        { t0 = (const char*)e0; t1 = (const char*)e3; }  // h_B

    int n = g_cur[b];
    if (n > KSLOT) n = KSLOT;

    float4 acc = __ldg(&bias4[c]);
    const int4* ep4 = reinterpret_cast<const int4*>(g_entries + b * KSLOT);
    int coff = c << 4;                     // c * 16 bytes

    int nfull = n & ~3;
    int j = 0;
    for (; j < nfull; j += 4) {
        int4 e4 = ep4[j >> 2];
        int ents[4] = {e4.x, e4.y, e4.z, e4.w};
        #pragma unroll
        for (int k = 0; k < 4; k++) {
            int ent = ents[k];
            const char* tb = (ent & ENT_FLAG_BIT) ? t1 : t0;
            const float4 v = *reinterpret_cast<const float4*>(
                tb + (ent & ENT_OFF_MASK) + coff);
            acc.x += v.x; acc.y += v.y; acc.z += v.z; acc.w += v.w;
        }
    }
    if (j < n) {                           // predicated tail group
        int4 e4 = ep4[j >> 2];
        int ents[4] = {e4.x, e4.y, e4.z, e4.w};
        #pragma unroll
        for (int k = 0; k < 4; k++) {
            if (j + k < n) {
                int ent = ents[k];
                const char* tb = (ent & ENT_FLAG_BIT) ? t1 : t0;
                const float4 v = *reinterpret_cast<const float4*>(
                    tb + (ent & ENT_OFF_MASK) + coff);
                acc.x += v.x; acc.y += v.y; acc.z += v.z; acc.w += v.w;
            }
        }
    }

    // overflow path: never taken in practice (one broadcast-cached load)
    int nov = g_cur[NOVER_IDX];
    if (nov > 0) {
        for (int jj = 0; jj < nov; jj++) {
            int2 se = g_spill[jj];
            if (se.x == b) {
                const char* tb = (se.y & ENT_FLAG_BIT) ? t1 : t0;
                const float4 v = *reinterpret_cast<const float4*>(
                    tb + (se.y & ENT_OFF_MASK) + coff);
                acc.x += v.x; acc.y += v.y; acc.z += v.z; acc.w += v.w;
            }
        }
    }

    acc.x = fmaxf(acc.x, 0.f);
    acc.y = fmaxf(acc.y, 0.f);
    acc.z = fmaxf(acc.z, 0.f);
    acc.w = fmaxf(acc.w, 0.f);
    __stcs(&out4[(long long)b * CHUNKS + c], acc);   // write-once output
}

// ---------------------------------------------------------------------------
// fallback path (atomic scatter, proven) if shapes exceed static scratch.
// Does not touch the bucket scratch at all.
// ---------------------------------------------------------------------------
__global__ void fb_init_kernel(float4* __restrict__ out,
                               const float4* __restrict__ bias4, int n4) {
    int i = blockIdx.x * blockDim.x + threadIdx.x;
    if (i < n4) out[i] = __ldg(&bias4[i & 15]);
}

__global__ void __launch_bounds__(256)
fb_scatter_kernel(const float* __restrict__ e0, const float* __restrict__ e1,
                  const float* __restrict__ e2, const float* __restrict__ e3,
                  const void* __restrict__ s0, const void* __restrict__ d0,
                  const void* __restrict__ s1, const void* __restrict__ d1,
                  const void* __restrict__ s2, const void* __restrict__ d2,
                  const void* __restrict__ s3, const void* __restrict__ d3,
                  float* __restrict__ out, int nE, long long nN) {
    int g = blockIdx.x * blockDim.x + threadIdx.x;
    int edge = g >> 4;
    int c = g & 15;
    if (edge >= nE) return;
    const float* emb; const void* sp; const void* dp; long long off;
    switch (blockIdx.y) {
        case 0:  emb = e0; sp = s0; dp = d0; off = nN * DIM; break;
        case 1:  emb = e1; sp = s1; dp = d1; off = 0;        break;
        case 2:  emb = e2; sp = s2; dp = d2; off = 0;        break;
        default: emb = e3; sp = s3; dp = d3; off = nN * DIM; break;
    }
    const int idx64 = probe_idx64((const unsigned int*)s0);
    long long src = load_idx32(sp, edge, idx64);
    long long dst = load_idx32(dp, edge, idx64);
    const float4 v =
        *reinterpret_cast<const float4*>(emb + src * DIM + (long long)c * 4);
    float* p = out + off + dst * DIM + (long long)c * 4;
    asm volatile("red.global.add.v4.f32 [%0], {%1,%2,%3,%4};"
                 :: "l"(p), "f"(v.x), "f"(v.y), "f"(v.z), "f"(v.w) : "memory");
}

__global__ void fb_relu_kernel(float4* __restrict__ out, int n4) {
    int i = blockIdx.x * blockDim.x + threadIdx.x;
    if (i >= n4) return;
    float4 v = out[i];
    v.x = fmaxf(v.x, 0.f); v.y = fmaxf(v.y, 0.f);
    v.z = fmaxf(v.z, 0.f); v.w = fmaxf(v.w, 0.f);
    out[i] = v;
}

// ---------------------------------------------------------------------------
// kernel_launch — inputs: embed0..3, h_bias, src0,dst0,...,src3,dst3
// ---------------------------------------------------------------------------
extern "C" void kernel_launch(void* const* d_in, const int* in_sizes, int n_in,
                              void* d_out, int out_size) {
    const float* e0 = (const float*)d_in[0];
    const float* e1 = (const float*)d_in[1];
    const float* e2 = (const float*)d_in[2];
    const float* e3 = (const float*)d_in[3];
    const float4* bias4 = (const float4*)d_in[4];

    const int nN = in_sizes[0] / DIM;      // 100000
    const int nE = in_sizes[5];            // 500000
    const int n4 = out_size / 4;           // 2*N*16

    float* out = (float*)d_out;
    const int T = 256;
    const int nb = 2 * nN;

    // entry encoding requires src*256 < 2^28
    if (nN <= NMAX && nE <= EMAX && nN < (1 << 20)) {
        // 1) zero cursors + overflow count with one async memset (graph
        //    memset node — no kernel launch, no allocation)
        void* curAddr = nullptr;
        cudaGetSymbolAddress(&curAddr, g_cur);
        cudaMemsetAsync(curAddr, 0, (size_t)(2 * NMAX + 1) * sizeof(int), 0);

        // 2) slot edges into buckets (all 4 relations per thread)
        permute_kernel<<<(nE + T - 1) / T, T>>>(
            d_in[5], d_in[6], d_in[7], d_in[8],
            d_in[9], d_in[10], d_in[11], d_in[12], nE, nN);

        // 3) gather-accumulate + bias + relu + store
        int work = nb * CHUNKS;
        accum_kernel<<<(work + T - 1) / T, T>>>(e0, e1, e2, e3, bias4,
                                                (float4*)out, nN);
    } else {
        // fallback: atomic scatter
        fb_init_kernel<<<(n4 + T - 1) / T, T>>>((float4*)out, bias4, n4);
        int work = nE * CHUNKS;
        dim3 grid((work + T - 1) / T, 4);
        fb_scatter_kernel<<<grid, T>>>(e0, e1, e2, e3,
                                       d_in[5], d_in[6], d_in[7], d_in[8],
                                       d_in[9], d_in[10], d_in[11], d_in[12],
                                       out, nE, nN);
        fb_relu_kernel<<<(n4 + T - 1) / T, T>>>((float4*)out, n4);
    }
}

// round 16
// speedup vs baseline: 1.0535x; 1.0535x over previous
#include <cuda_runtime.h>
#include <cstdint>

#define DIM     64
#define CHUNKS  16            // float4 chunks per row
#define NMAX    100000        // nodes per ntype (static scratch sizing)
#define EMAX    500000        // edges per relation
#define KSLOT   40            // slots per bucket (deg ~Poisson(10)); 160B, 16B-aligned
#define SPILLC  (4 * EMAX)    // spill capacity = all edges (unconditional)
#define NOVER_IDX (2 * NMAX)  // overflow counter lives at g_cur[NOVER_IDX]

// entry encoding: bits [8..27] = src*256 (byte offset into embed table),
//                 bit 30 = table flag. Requires src*256 < 2^28 (N < 1M).
#define ENT_OFF_MASK 0x0FFFFFFF
#define ENT_FLAG_BIT (1 << 30)

// ---------------------------------------------------------------------------
// scratch (device globals — no runtime allocation). g_cur[0..2*NMAX) are the
// per-bucket cursors; g_cur[2*NMAX] is the overflow count. One memset clears
// everything before permute.
// ---------------------------------------------------------------------------
__device__ int  g_cur[2 * NMAX + 1];
__device__ int  g_entries[2 * NMAX * KSLOT];  // (src<<8) | (flag<<30), slotted
__device__ int2 g_spill[SPILLC];              // (bucket, entry)

// ---------------------------------------------------------------------------
// index helpers. int64 values in [0,1e5): odd 32-bit words are 0.
// int32 random values: P(4 specific words all 0) ~ 1e-20. Broadcast loads.
// ---------------------------------------------------------------------------
__device__ __forceinline__ int probe_idx64(const unsigned int* __restrict__ w) {
    return ((w[1] | w[3] | w[5] | w[7]) == 0u) ? 1 : 0;
}
__device__ __forceinline__ int load_idx32(const void* p, int i, int idx64) {
    // index values < 2^31: low word suffices for both int32 and int64 layouts
    return idx64 ? ((const int*)p)[2 * i] : ((const int*)p)[i];
}

// ---------------------------------------------------------------------------
// 1) permute (R14-proven): slot edges into per-bucket regions. gridDim.y =
//    relation. r0:(B,e0) r1:(A,e1) r2:(A,e2) r3:(B,e3).
//    bucket b = ntype*nN + dst; entry carries precomputed byte offset + flag.
//    Overflow (pos >= KSLOT) goes to the spill list (sized for ALL edges).
// ---------------------------------------------------------------------------
__global__ void __launch_bounds__(256)
permute_kernel(const void* __restrict__ s0, const void* __restrict__ d0,
               const void* __restrict__ s1, const void* __restrict__ d1,
               const void* __restrict__ s2, const void* __restrict__ d2,
               const void* __restrict__ s3, const void* __restrict__ d3,
               int nE, int nN) {
    int e = blockIdx.x * blockDim.x + threadIdx.x;
    if (e >= nE) return;
    int r = blockIdx.y;

    const void* sp; const void* dp; int ntype; int flag;
    switch (r) {
        case 0:  sp = s0; dp = d0; ntype = 1; flag = 0; break;
        case 1:  sp = s1; dp = d1; ntype = 0; flag = 0; break;
        case 2:  sp = s2; dp = d2; ntype = 0; flag = 1; break;
        default: sp = s3; dp = d3; ntype = 1; flag = 1; break;
    }

    const int idx64 = probe_idx64((const unsigned int*)s0);
    int src = load_idx32(sp, e, idx64);
    int dst = load_idx32(dp, e, idx64);
    int b = ntype * nN + dst;
    int ent = (src << 8) | (flag << 30);   // byte offset (src*256) + table flag

    int pos = atomicAdd(&g_cur[b], 1);
    if (pos < KSLOT) {
        g_entries[b * KSLOT + pos] = ent;
    } else {
        int spos = atomicAdd(&g_cur[NOVER_IDX], 1);
        g_spill[spos] = make_int2(b, ent);
    }
}

// ---------------------------------------------------------------------------
// 2) accumulate (R14 shape + next-group prefetch): thread = (bucket, chunk).
//    Seed = bias (broadcast), register-accumulate gathered rows, relu,
//    single streaming store. bucket < nN -> h_A (e1/e2), else h_B (e0/e3).
//    Entries fetched 4-at-a-time via int4; the NEXT group's entry load is
//    issued before the current group's gathers so it overlaps their latency.
// ---------------------------------------------------------------------------
__global__ void __launch_bounds__(256)
accum_kernel(const float* __restrict__ e0, const float* __restrict__ e1,
             const float* __restrict__ e2, const float* __restrict__ e3,
             const float4* __restrict__ bias4, float4* __restrict__ out4,
             int nN) {
    int g = blockIdx.x * blockDim.x + threadIdx.x;
    int b = g >> 4;
    int c = g & 15;
    if (b >= 2 * nN) return;

    const char* t0;
    const char* t1;
    if (b < nN) { t0 = (const char*)e1; t1 = (const char*)e2; }  // h_A
    else        { t0 = (const char*)e0; t1 = (const char*)e3; }  // h_B

    int n = g_cur[b];
    if (n > KSLOT) n = KSLOT;

    float4 acc = __ldg(&bias4[c]);
    const int4* ep4 = reinterpret_cast<const int4*>(g_entries + b * KSLOT);
    int coff = c << 4;                     // c * 16 bytes

    if (n > 0) {
        int4 nxt = ep4[0];
        for (int j = 0; j < n; j += 4) {
            int4 cur = nxt;
            if (j + 4 < n) nxt = ep4[(j >> 2) + 1];   // prefetch next group
            int ents[4] = {cur.x, cur.y, cur.z, cur.w};
            #pragma unroll
            for (int k = 0; k < 4; k++) {
                if (j + k < n) {
                    int ent = ents[k];
                    const char* tb = (ent & ENT_FLAG_BIT) ? t1 : t0;
                    const float4 v = *reinterpret_cast<const float4*>(
                        tb + (ent & ENT_OFF_MASK) + coff);
                    acc.x += v.x; acc.y += v.y; acc.z += v.z; acc.w += v.w;
                }
            }
        }
    }

    // overflow path: never taken in practice (one broadcast-cached load)
    int nov = g_cur[NOVER_IDX];
    if (nov > 0) {
        for (int j = 0; j < nov; j++) {
            int2 se = g_spill[j];
            if (se.x == b) {
                const char* tb = (se.y & ENT_FLAG_BIT) ? t1 : t0;
                const float4 v = *reinterpret_cast<const float4*>(
                    tb + (se.y & ENT_OFF_MASK) + coff);
                acc.x += v.x; acc.y += v.y; acc.z += v.z; acc.w += v.w;
            }
        }
    }

    acc.x = fmaxf(acc.x, 0.f);
    acc.y = fmaxf(acc.y, 0.f);
    acc.z = fmaxf(acc.z, 0.f);
    acc.w = fmaxf(acc.w, 0.f);
    __stcs(&out4[(long long)b * CHUNKS + c], acc);   // write-once output
}

// ---------------------------------------------------------------------------
// fallback path (atomic scatter, proven) if shapes exceed static scratch.
// Does not touch the bucket scratch at all.
// ---------------------------------------------------------------------------
__global__ void fb_init_kernel(float4* __restrict__ out,
                               const float4* __restrict__ bias4, int n4) {
    int i = blockIdx.x * blockDim.x + threadIdx.x;
    if (i < n4) out[i] = __ldg(&bias4[i & 15]);
}

__global__ void __launch_bounds__(256)
fb_scatter_kernel(const float* __restrict__ e0, const float* __restrict__ e1,
                  const float* __restrict__ e2, const float* __restrict__ e3,
                  const void* __restrict__ s0, const void* __restrict__ d0,
                  const void* __restrict__ s1, const void* __restrict__ d1,
                  const void* __restrict__ s2, const void* __restrict__ d2,
                  const void* __restrict__ s3, const void* __restrict__ d3,
                  float* __restrict__ out, int nE, long long nN) {
    int g = blockIdx.x * blockDim.x + threadIdx.x;
    int edge = g >> 4;
    int c = g & 15;
    if (edge >= nE) return;
    const float* emb; const void* sp; const void* dp; long long off;
    switch (blockIdx.y) {
        case 0:  emb = e0; sp = s0; dp = d0; off = nN * DIM; break;
        case 1:  emb = e1; sp = s1; dp = d1; off = 0;        break;
        case 2:  emb = e2; sp = s2; dp = d2; off = 0;        break;
        default: emb = e3; sp = s3; dp = d3; off = nN * DIM; break;
    }
    const int idx64 = probe_idx64((const unsigned int*)s0);
    long long src = load_idx32(sp, edge, idx64);
    long long dst = load_idx32(dp, edge, idx64);
    const float4 v =
        *reinterpret_cast<const float4*>(emb + src * DIM + (long long)c * 4);
    float* p = out + off + dst * DIM + (long long)c * 4;
    asm volatile("red.global.add.v4.f32 [%0], {%1,%2,%3,%4};"
                 :: "l"(p), "f"(v.x), "f"(v.y), "f"(v.z), "f"(v.w) : "memory");
}

__global__ void fb_relu_kernel(float4* __restrict__ out, int n4) {
    int i = blockIdx.x * blockDim.x + threadIdx.x;
    if (i >= n4) return;
    float4 v = out[i];
    v.x = fmaxf(v.x, 0.f); v.y = fmaxf(v.y, 0.f);
    v.z = fmaxf(v.z, 0.f); v.w = fmaxf(v.w, 0.f);
    out[i] = v;
}

// ---------------------------------------------------------------------------
// kernel_launch — inputs: embed0..3, h_bias, src0,dst0,...,src3,dst3
// ---------------------------------------------------------------------------
extern "C" void kernel_launch(void* const* d_in, const int* in_sizes, int n_in,
                              void* d_out, int out_size) {
    const float* e0 = (const float*)d_in[0];
    const float* e1 = (const float*)d_in[1];
    const float* e2 = (const float*)d_in[2];
    const float* e3 = (const float*)d_in[3];
    const float4* bias4 = (const float4*)d_in[4];

    const int nN = in_sizes[0] / DIM;      // 100000
    const int nE = in_sizes[5];            // 500000
    const int n4 = out_size / 4;           // 2*N*16

    float* out = (float*)d_out;
    const int T = 256;
    const int nb = 2 * nN;

    // entry encoding requires src*256 < 2^28
    if (nN <= NMAX && nE <= EMAX && nN < (1 << 20)) {
        // 1) zero cursors + overflow count with one async memset (graph
        //    memset node — no kernel launch, no allocation)
        void* curAddr = nullptr;
        cudaGetSymbolAddress(&curAddr, g_cur);
        cudaMemsetAsync(curAddr, 0, (size_t)(2 * NMAX + 1) * sizeof(int), 0);

        // 2) slot edges into buckets
        dim3 gperm((nE + T - 1) / T, 4);
        permute_kernel<<<gperm, T>>>(d_in[5], d_in[6], d_in[7], d_in[8],
                                     d_in[9], d_in[10], d_in[11], d_in[12],
                                     nE, nN);
        // 3) gather-accumulate + bias + relu + store
        int work = nb * CHUNKS;
        accum_kernel<<<(work + T - 1) / T, T>>>(e0, e1, e2, e3, bias4,
                                                (float4*)out, nN);
    } else {
        // fallback: atomic scatter
        fb_init_kernel<<<(n4 + T - 1) / T, T>>>((float4*)out, bias4, n4);
        int work = nE * CHUNKS;
        dim3 grid((work + T - 1) / T, 4);
        fb_scatter_kernel<<<grid, T>>>(e0, e1, e2, e3,
                                       d_in[5], d_in[6], d_in[7], d_in[8],
                                       d_in[9], d_in[10], d_in[11], d_in[12],
                                       out, nE, nN);
        fb_relu_kernel<<<(n4 + T - 1) / T, T>>>((float4*)out, n4);
    }
}

// round 17
// speedup vs baseline: 1.1362x; 1.0785x over previous
#include <cuda_runtime.h>
#include <cstdint>

#define DIM     64
#define CHUNKS  16            // float4 chunks per row
#define NMAX    100000        // nodes per ntype (static scratch sizing)
#define EMAX    500000        // edges per relation
#define KSLOT   40            // slots per bucket (deg ~Poisson(10)); 160B, 16B-aligned
#define SPILLC  (4 * EMAX)    // spill capacity = all edges (unconditional)
#define NOVER_IDX (2 * NMAX)  // overflow counter lives at g_cur[NOVER_IDX]

// entry encoding: bits [8..27] = src*256 (byte offset into embed table),
//                 bit 30 = table flag. Requires src*256 < 2^28 (N < 1M).
#define ENT_OFF_MASK 0x0FFFFFFF
#define ENT_FLAG_BIT (1 << 30)

// ---------------------------------------------------------------------------
// scratch (device globals — no runtime allocation). g_cur[0..2*NMAX) are the
// per-bucket cursors; g_cur[2*NMAX] is the overflow count. One memset clears
// everything before permute.
// ---------------------------------------------------------------------------
__device__ int  g_cur[2 * NMAX + 1];
__device__ int  g_entries[2 * NMAX * KSLOT];  // (src<<8) | (flag<<30), slotted
__device__ int2 g_spill[SPILLC];              // (bucket, entry)

// ---------------------------------------------------------------------------
// index helpers. int64 values in [0,1e5): odd 32-bit words are 0.
// int32 random values: P(4 specific words all 0) ~ 1e-20. Broadcast loads.
// ---------------------------------------------------------------------------
__device__ __forceinline__ int probe_idx64(const unsigned int* __restrict__ w) {
    return ((w[1] | w[3] | w[5] | w[7]) == 0u) ? 1 : 0;
}
__device__ __forceinline__ int load_idx32(const void* p, int i, int idx64) {
    // index values < 2^31: low word suffices for both int32 and int64 layouts
    return idx64 ? ((const int*)p)[2 * i] : ((const int*)p)[i];
}

// ---------------------------------------------------------------------------
// 1) permute: slot edges into per-bucket regions. gridDim.y = relation.
//    relation -> (dst ntype, src table): r0:(B,e0) r1:(A,e1) r2:(A,e2) r3:(B,e3)
//    bucket b = ntype*nN + dst; entry carries precomputed byte offset + flag.
//    Overflow (pos >= KSLOT) goes to the spill list (sized for ALL edges).
// ---------------------------------------------------------------------------
__global__ void __launch_bounds__(256)
permute_kernel(const void* __restrict__ s0, const void* __restrict__ d0,
               const void* __restrict__ s1, const void* __restrict__ d1,
               const void* __restrict__ s2, const void* __restrict__ d2,
               const void* __restrict__ s3, const void* __restrict__ d3,
               int nE, int nN) {
    int e = blockIdx.x * blockDim.x + threadIdx.x;
    if (e >= nE) return;
    int r = blockIdx.y;

    const void* sp; const void* dp; int ntype; int flag;
    switch (r) {
        case 0:  sp = s0; dp = d0; ntype = 1; flag = 0; break;
        case 1:  sp = s1; dp = d1; ntype = 0; flag = 0; break;
        case 2:  sp = s2; dp = d2; ntype = 0; flag = 1; break;
        default: sp = s3; dp = d3; ntype = 1; flag = 1; break;
    }

    const int idx64 = probe_idx64((const unsigned int*)s0);
    int src = load_idx32(sp, e, idx64);
    int dst = load_idx32(dp, e, idx64);
    int b = ntype * nN + dst;
    int ent = (src << 8) | (flag << 30);   // byte offset (src*256) + table flag

    int pos = atomicAdd(&g_cur[b], 1);
    if (pos < KSLOT) {
        g_entries[b * KSLOT + pos] = ent;
    } else {
        int spos = atomicAdd(&g_cur[NOVER_IDX], 1);
        g_spill[spos] = make_int2(b, ent);
    }
}

// ---------------------------------------------------------------------------
// 2) accumulate: thread = (bucket, float4-chunk). Seed = bias (broadcast),
//    register-accumulate gathered rows, relu, single streaming store.
//    bucket < nN -> h_A (tables e1/e2), else h_B (tables e0/e3).
//    Entries fetched 4-at-a-time via int4; entry already holds the row byte
//    offset, so the gather address is a single LEA. Output stored with .cs
//    (write-once) to avoid evicting embed-table lines from L2.
// ---------------------------------------------------------------------------
__global__ void __launch_bounds__(256)
accum_kernel(const float* __restrict__ e0, const float* __restrict__ e1,
             const float* __restrict__ e2, const float* __restrict__ e3,
             const float4* __restrict__ bias4, float4* __restrict__ out4,
             int nN) {
    int g = blockIdx.x * blockDim.x + threadIdx.x;
    int b = g >> 4;
    int c = g & 15;
    if (b >= 2 * nN) return;

    const char* t0;
    const char* t1;
    if (b < nN) { t0 = (const char*)e1; t1 = (const char*)e2; }  // h_A
    else        { t0 = (const char*)e0; t1 = (const char*)e3; }  // h_B

    int n = g_cur[b];
    if (n > KSLOT) n = KSLOT;

    float4 acc = __ldg(&bias4[c]);
    const int4* ep4 = reinterpret_cast<const int4*>(g_entries + b * KSLOT);
    int coff = c << 4;                     // c * 16 bytes

    for (int j = 0; j < n; j += 4) {
        int4 e4 = ep4[j >> 2];
        int ents[4] = {e4.x, e4.y, e4.z, e4.w};
        #pragma unroll
        for (int k = 0; k < 4; k++) {
            if (j + k < n) {
                int ent = ents[k];
                const char* tb = (ent & ENT_FLAG_BIT) ? t1 : t0;
                const float4 v = *reinterpret_cast<const float4*>(
                    tb + (ent & ENT_OFF_MASK) + coff);
                acc.x += v.x; acc.y += v.y; acc.z += v.z; acc.w += v.w;
            }
        }
    }

    // overflow path: never taken in practice (one broadcast-cached load)
    int nov = g_cur[NOVER_IDX];
    if (nov > 0) {
        for (int j = 0; j < nov; j++) {
            int2 se = g_spill[j];
            if (se.x == b) {
                const char* tb = (se.y & ENT_FLAG_BIT) ? t1 : t0;
                const float4 v = *reinterpret_cast<const float4*>(
                    tb + (se.y & ENT_OFF_MASK) + coff);
                acc.x += v.x; acc.y += v.y; acc.z += v.z; acc.w += v.w;
            }
        }
    }

    acc.x = fmaxf(acc.x, 0.f);
    acc.y = fmaxf(acc.y, 0.f);
    acc.z = fmaxf(acc.z, 0.f);
    acc.w = fmaxf(acc.w, 0.f);
    __stcs(&out4[(long long)b * CHUNKS + c], acc);   // write-once output
}

// ---------------------------------------------------------------------------
// fallback path (atomic scatter, proven) if shapes exceed static scratch.
// Does not touch the bucket scratch at all.
// ---------------------------------------------------------------------------
__global__ void fb_init_kernel(float4* __restrict__ out,
                               const float4* __restrict__ bias4, int n4) {
    int i = blockIdx.x * blockDim.x + threadIdx.x;
    if (i < n4) out[i] = __ldg(&bias4[i & 15]);
}

__global__ void __launch_bounds__(256)
fb_scatter_kernel(const float* __restrict__ e0, const float* __restrict__ e1,
                  const float* __restrict__ e2, const float* __restrict__ e3,
                  const void* __restrict__ s0, const void* __restrict__ d0,
                  const void* __restrict__ s1, const void* __restrict__ d1,
                  const void* __restrict__ s2, const void* __restrict__ d2,
                  const void* __restrict__ s3, const void* __restrict__ d3,
                  float* __restrict__ out, int nE, long long nN) {
    int g = blockIdx.x * blockDim.x + threadIdx.x;
    int edge = g >> 4;
    int c = g & 15;
    if (edge >= nE) return;
    const float* emb; const void* sp; const void* dp; long long off;
    switch (blockIdx.y) {
        case 0:  emb = e0; sp = s0; dp = d0; off = nN * DIM; break;
        case 1:  emb = e1; sp = s1; dp = d1; off = 0;        break;
        case 2:  emb = e2; sp = s2; dp = d2; off = 0;        break;
        default: emb = e3; sp = s3; dp = d3; off = nN * DIM; break;
    }
    const int idx64 = probe_idx64((const unsigned int*)s0);
    long long src = load_idx32(sp, edge, idx64);
    long long dst = load_idx32(dp, edge, idx64);
    const float4 v =
        *reinterpret_cast<const float4*>(emb + src * DIM + (long long)c * 4);
    float* p = out + off + dst * DIM + (long long)c * 4;
    asm volatile("red.global.add.v4.f32 [%0], {%1,%2,%3,%4};"
                 :: "l"(p), "f"(v.x), "f"(v.y), "f"(v.z), "f"(v.w) : "memory");
}

__global__ void fb_relu_kernel(float4* __restrict__ out, int n4) {
    int i = blockIdx.x * blockDim.x + threadIdx.x;
    if (i >= n4) return;
    float4 v = out[i];
    v.x = fmaxf(v.x, 0.f); v.y = fmaxf(v.y, 0.f);
    v.z = fmaxf(v.z, 0.f); v.w = fmaxf(v.w, 0.f);
    out[i] = v;
}

// ---------------------------------------------------------------------------
// kernel_launch — inputs: embed0..3, h_bias, src0,dst0,...,src3,dst3
// ---------------------------------------------------------------------------
extern "C" void kernel_launch(void* const* d_in, const int* in_sizes, int n_in,
                              void* d_out, int out_size) {
    const float* e0 = (const float*)d_in[0];
    const float* e1 = (const float*)d_in[1];
    const float* e2 = (const float*)d_in[2];
    const float* e3 = (const float*)d_in[3];
    const float4* bias4 = (const float4*)d_in[4];

    const int nN = in_sizes[0] / DIM;      // 100000
    const int nE = in_sizes[5];            // 500000
    const int n4 = out_size / 4;           // 2*N*16

    float* out = (float*)d_out;
    const int T = 256;
    const int nb = 2 * nN;

    // entry encoding requires src*256 < 2^28
    if (nN <= NMAX && nE <= EMAX && nN < (1 << 20)) {
        // 1) zero cursors + overflow count with one async memset (graph
        //    memset node — no kernel launch, no allocation)
        void* curAddr = nullptr;
        cudaGetSymbolAddress(&curAddr, g_cur);
        cudaMemsetAsync(curAddr, 0, (size_t)(2 * NMAX + 1) * sizeof(int), 0);

        // 2) slot edges into buckets
        dim3 gperm((nE + T - 1) / T, 4);
        permute_kernel<<<gperm, T>>>(d_in[5], d_in[6], d_in[7], d_in[8],
                                     d_in[9], d_in[10], d_in[11], d_in[12],
                                     nE, nN);
        // 3) gather-accumulate + bias + relu + store
        int work = nb * CHUNKS;
        accum_kernel<<<(work + T - 1) / T, T>>>(e0, e1, e2, e3, bias4,
                                                (float4*)out, nN);
    } else {
        // fallback: atomic scatter
        fb_init_kernel<<<(n4 + T - 1) / T, T>>>((float4*)out, bias4, n4);
        int work = nE * CHUNKS;
        dim3 grid((work + T - 1) / T, 4);
        fb_scatter_kernel<<<grid, T>>>(e0, e1, e2, e3,
                                       d_in[5], d_in[6], d_in[7], d_in[8],
                                       d_in[9], d_in[10], d_in[11], d_in[12],
                                       out, nE, nN);
        fb_relu_kernel<<<(n4 + T - 1) / T, T>>>((float4*)out, n4);
    }
}